// round 16
// baseline (speedup 1.0000x reference)
#include <cuda_runtime.h>

#define LSEQ 256
#define CIN  8
#define COUT 8
#define HID  32
#define XPAD 12     // sx row stride (floats): conflict-free LDS.128
#define H1PAD 36    // sh1 row stride
#define W2PAD 36    // sW2 row stride: conflict-free broadcast loads
#define NBLK 256    // 8 o x 32 d-tiles  (>=148: SM issue-throttle off)
#define NTHR 256

// ---------------------------------------------------------------------------
// Kernel 0: zero the output (each graph replay re-accumulates).
// ---------------------------------------------------------------------------
__global__ void zero_out(float* __restrict__ out)
{
    ((float4*)out)[threadIdx.x] = make_float4(0.f, 0.f, 0.f, 0.f);  // 512 f4
}

// ---------------------------------------------------------------------------
// PUSH kernel: 256 blocks x 256 threads, 2 CTAs/SM, no inter-block sync.
// Block (o = bid>>5, t = bid&31) evaluates the SIREN net on its 64 points
// (d in [8t, 8t+8), c in [0,8)), keeps K in smem, then pushes its taps'
// contributions to all downstream outputs via one atomicAdd per thread.
// ---------------------------------------------------------------------------
__global__ __launch_bounds__(NTHR, 2) void ckconv_push(
    const float* __restrict__ x,
    const float* __restrict__ v1, const float* __restrict__ g1,
    const float* __restrict__ b1,
    const float* __restrict__ v2, const float* __restrict__ g2,
    const float* __restrict__ b2,
    const float* __restrict__ w3, const float* __restrict__ b3,
    float* __restrict__ out)
{
    __shared__ float  sW1[HID][3];
    __shared__ float  sb1[HID];
    __shared__ __align__(16) float sW2[HID * W2PAD];
    __shared__ float  sb2[HID];
    __shared__ float  sw3[HID];
    __shared__ float  sb3;
    __shared__ __align__(16) float sh1[64 * H1PAD];
    __shared__ __align__(16) float sk[64];         // K[dd][c], dd<8, c<8
    __shared__ __align__(16) float sx[LSEQ * XPAD];

    int tid = threadIdx.x;

    // ---------------- phase 0: stage x + weight prep ------------------------
    {
        int r = tid >> 1, hh = (tid & 1) << 2;
        *(float4*)&sx[r * XPAD + hh]         = ((const float4*)x)[tid];
        *(float4*)&sx[(r + 128) * XPAD + hh] = ((const float4*)x)[tid + 256];
    }
    {
        float4 w4 = ((const float4*)v2)[tid];          // 256 float4 = all of v2
        float ss = w4.x * w4.x + w4.y * w4.y + w4.z * w4.z + w4.w * w4.w;
        ss += __shfl_xor_sync(0xFFFFFFFFu, ss, 1);
        ss += __shfl_xor_sync(0xFFFFFFFFu, ss, 2);
        ss += __shfl_xor_sync(0xFFFFFFFFu, ss, 4);
        int row = tid >> 3;
        float inv = g2[row] * rsqrtf(ss);
        float4 nw;
        nw.x = w4.x * inv; nw.y = w4.y * inv; nw.z = w4.z * inv; nw.w = w4.w * inv;
        *(float4*)&sW2[row * W2PAD + ((tid & 7) << 2)] = nw;
    }
    if (tid < HID) {
        float a = v1[tid * 3 + 0];
        float b = v1[tid * 3 + 1];
        float c = v1[tid * 3 + 2];
        float inv1 = g1[tid] * rsqrtf(a * a + b * b + c * c);
        sW1[tid][0] = a * inv1;
        sW1[tid][1] = b * inv1;
        sW1[tid][2] = c * inv1;
        sb1[tid] = b1[tid];
        sb2[tid] = b2[tid];
        sw3[tid] = w3[tid];
        if (tid == 0) sb3 = b3[0];
    }
    __syncthreads();

    // ---------------- coordinates -------------------------------------------
    // Local point p = pp + 32i == dd*8 + c (dd < 8). 2 points per thread.
    int pp = tid >> 3;                         // 0..31
    int q  = tid & 7;
    int oc    = blockIdx.x >> 5;               // out channel
    int dbase = (blockIdx.x & 31) << 3;        // 8 d-values per block
    float fc = (float)(pp & 7);
    float fo = (float)oc;
    int d0 = dbase + (pp >> 3);                // point i: d = d0 + 4i, i<2

    // ---------------- phase 1a: h1[p][4q..4q+3] for 2 points ----------------
    {
        float4 hv[2];
        #pragma unroll
        for (int m = 0; m < 4; m++) {
            int h = (q << 2) + m;
            float zb = fmaf(fc, sW1[h][1], fmaf(fo, sW1[h][2], sb1[h]));
            float w0 = sW1[h][0];
            #pragma unroll
            for (int i = 0; i < 2; i++) {
                float dt = -(float)(d0 + (i << 2)) * (1.0f / 256.0f);
                ((float*)&hv[i])[m] = __sinf(fmaf(dt, w0, zb));  // OMEGA = 1
            }
        }
        #pragma unroll
        for (int i = 0; i < 2; i++)
            *(float4*)&sh1[(pp + (i << 5)) * H1PAD + (q << 2)] = hv[i];
    }
    __syncthreads();

    // ---------------- phase 1b: neurons k=q+8m, 2 points --------------------
    {
        const float* r0 = &sW2[(q     ) * W2PAD];
        const float* r1 = &sW2[(q +  8) * W2PAD];
        const float* r2 = &sW2[(q + 16) * W2PAD];
        const float* r3 = &sW2[(q + 24) * W2PAD];

        float z0[2], z1[2], z2[2], z3[2];
        #pragma unroll
        for (int i = 0; i < 2; i++) {
            z0[i] = sb2[q];
            z1[i] = sb2[q + 8];
            z2[i] = sb2[q + 16];
            z3[i] = sb2[q + 24];
        }

        #pragma unroll
        for (int j = 0; j < 8; j++) {
            float4 h[2];
            #pragma unroll
            for (int i = 0; i < 2; i++)
                h[i] = *(const float4*)&sh1[(pp + (i << 5)) * H1PAD + 4 * j];

            float4 w;
            w = *(const float4*)&r0[4 * j];
            #pragma unroll
            for (int i = 0; i < 2; i++) {
                z0[i] = fmaf(h[i].x, w.x, z0[i]); z0[i] = fmaf(h[i].y, w.y, z0[i]);
                z0[i] = fmaf(h[i].z, w.z, z0[i]); z0[i] = fmaf(h[i].w, w.w, z0[i]);
            }
            w = *(const float4*)&r1[4 * j];
            #pragma unroll
            for (int i = 0; i < 2; i++) {
                z1[i] = fmaf(h[i].x, w.x, z1[i]); z1[i] = fmaf(h[i].y, w.y, z1[i]);
                z1[i] = fmaf(h[i].z, w.z, z1[i]); z1[i] = fmaf(h[i].w, w.w, z1[i]);
            }
            w = *(const float4*)&r2[4 * j];
            #pragma unroll
            for (int i = 0; i < 2; i++) {
                z2[i] = fmaf(h[i].x, w.x, z2[i]); z2[i] = fmaf(h[i].y, w.y, z2[i]);
                z2[i] = fmaf(h[i].z, w.z, z2[i]); z2[i] = fmaf(h[i].w, w.w, z2[i]);
            }
            w = *(const float4*)&r3[4 * j];
            #pragma unroll
            for (int i = 0; i < 2; i++) {
                z3[i] = fmaf(h[i].x, w.x, z3[i]); z3[i] = fmaf(h[i].y, w.y, z3[i]);
                z3[i] = fmaf(h[i].z, w.z, z3[i]); z3[i] = fmaf(h[i].w, w.w, z3[i]);
            }
        }

        float s0 = sw3[q], s1 = sw3[q + 8], s2 = sw3[q + 16], s3 = sw3[q + 24];
        #pragma unroll
        for (int i = 0; i < 2; i++) {
            float acc =        __sinf(z0[i]) * s0;
            acc = fmaf(__sinf(z1[i]), s1, acc);
            acc = fmaf(__sinf(z2[i]), s2, acc);
            acc = fmaf(__sinf(z3[i]), s3, acc);
            acc += __shfl_xor_sync(0xFFFFFFFFu, acc, 1);
            acc += __shfl_xor_sync(0xFFFFFFFFu, acc, 2);
            acc += __shfl_xor_sync(0xFFFFFFFFu, acc, 4);
            if (q == 0)
                sk[pp + (i << 5)] = acc + sb3;    // == sk[dd*8 + c]
        }
    }
    __syncthreads();

    // ---------------- phase 2: conv push (no inter-block sync) --------------
    // Thread j handles output i = dbase + j; this block's taps dd in [0,8),
    // valid when dd <= j. x row = j - dd (tile-independent).
    {
        int j = tid;
        int i = dbase + j;
        if (i < LSEQ) {
            const float4* skv = (const float4*)sk;
            float accv = 0.f;
            #pragma unroll
            for (int dd = 0; dd < 8; dd++) {
                float4 k0 = skv[2 * dd];          // broadcast
                float4 k1 = skv[2 * dd + 1];
                int jr = j - dd;
                bool v = jr >= 0;
                int jx = v ? jr : 0;
                float mm = v ? 1.f : 0.f;
                float4 a0 = *(const float4*)&sx[jx * XPAD];
                float4 b0 = *(const float4*)&sx[jx * XPAD + 4];
                float t = k0.x * a0.x;
                t = fmaf(k0.y, a0.y, t);
                t = fmaf(k0.z, a0.z, t);
                t = fmaf(k0.w, a0.w, t);
                t = fmaf(k1.x, b0.x, t);
                t = fmaf(k1.y, b0.y, t);
                t = fmaf(k1.z, b0.z, t);
                t = fmaf(k1.w, b0.w, t);
                accv = fmaf(mm, t, accv);
            }
            atomicAdd(out + i * COUT + oc, accv);  // fire-and-forget REDG
        }
    }
}

// ---------------------------------------------------------------------------
// Launch: zero out, then push-accumulate. Both graph-capturable.
// Input order: x, t, v1, g1, b1, v2, g2, b2, w3, b3 (t folded analytically).
// ---------------------------------------------------------------------------
extern "C" void kernel_launch(void* const* d_in, const int* in_sizes, int n_in,
                              void* d_out, int out_size)
{
    const float* x  = (const float*)d_in[0];
    const float* v1 = (const float*)d_in[2];
    const float* g1 = (const float*)d_in[3];
    const float* b1 = (const float*)d_in[4];
    const float* v2 = (const float*)d_in[5];
    const float* g2 = (const float*)d_in[6];
    const float* b2 = (const float*)d_in[7];
    const float* w3 = (const float*)d_in[8];
    const float* b3 = (const float*)d_in[9];
    float* out = (float*)d_out;

    zero_out<<<1, 512>>>(out);                  // 2048 floats
    ckconv_push<<<NBLK, NTHR>>>(x, v1, g1, b1, v2, g2, b2, w3, b3, out);
}

// round 17
// speedup vs baseline: 1.9136x; 1.9136x over previous
#include <cuda_runtime.h>

#define LSEQ 256
#define CIN  8
#define COUT 8
#define HID  32
#define XPAD 12     // sx row stride (floats): conflict-free LDS.128 at stride 12
#define H1PAD 36    // sh1 row stride
#define W2PAD 36    // sW2 row stride: conflict-free broadcast loads
#define NBLK 128
#define NTHR 256

// ---------------------------------------------------------------------------
// PUSH kernel (R15 champion, unchanged): 128 blocks x 256 threads, no
// inter-block sync. Block (o = bid>>4, t = bid&15) evaluates the SIREN
// kernel-net on its 128 points (d in [16t,16t+16), c in [0,8)), keeps K in
// block smem, then pushes its d-tile's conv contributions to
// out[i = 16t + j, o] via one atomicAdd per thread.
// ---------------------------------------------------------------------------
__global__ __launch_bounds__(NTHR, 1) void ckconv_push(
    const float* __restrict__ x,
    const float* __restrict__ v1, const float* __restrict__ g1,
    const float* __restrict__ b1,
    const float* __restrict__ v2, const float* __restrict__ g2,
    const float* __restrict__ b2,
    const float* __restrict__ w3, const float* __restrict__ b3,
    float* __restrict__ out)
{
    __shared__ float  sW1[HID][3];
    __shared__ float  sb1[HID];
    __shared__ __align__(16) float sW2[HID * W2PAD];
    __shared__ float  sb2[HID];
    __shared__ float  sw3[HID];
    __shared__ float  sb3;
    __shared__ __align__(16) float sh1[128 * H1PAD];
    __shared__ __align__(16) float sk[128];        // K[dd][c], dd<16, c<8
    __shared__ __align__(16) float sx[LSEQ * XPAD];

    int tid = threadIdx.x;

    // ---------------- phase 0: stage x + weight prep ------------------------
    {
        int r = tid >> 1, hh = (tid & 1) << 2;
        *(float4*)&sx[r * XPAD + hh]         = ((const float4*)x)[tid];
        *(float4*)&sx[(r + 128) * XPAD + hh] = ((const float4*)x)[tid + 256];
    }
    {
        float4 w4 = ((const float4*)v2)[tid];          // 256 float4 = all of v2
        float ss = w4.x * w4.x + w4.y * w4.y + w4.z * w4.z + w4.w * w4.w;
        ss += __shfl_xor_sync(0xFFFFFFFFu, ss, 1);
        ss += __shfl_xor_sync(0xFFFFFFFFu, ss, 2);
        ss += __shfl_xor_sync(0xFFFFFFFFu, ss, 4);
        int row = tid >> 3;
        float inv = g2[row] * rsqrtf(ss);
        float4 nw;
        nw.x = w4.x * inv; nw.y = w4.y * inv; nw.z = w4.z * inv; nw.w = w4.w * inv;
        *(float4*)&sW2[row * W2PAD + ((tid & 7) << 2)] = nw;
    }
    if (tid < HID) {
        float a = v1[tid * 3 + 0];
        float b = v1[tid * 3 + 1];
        float c = v1[tid * 3 + 2];
        float inv1 = g1[tid] * rsqrtf(a * a + b * b + c * c);
        sW1[tid][0] = a * inv1;
        sW1[tid][1] = b * inv1;
        sW1[tid][2] = c * inv1;
        sb1[tid] = b1[tid];
        sb2[tid] = b2[tid];
        sw3[tid] = w3[tid];
        if (tid == 0) sb3 = b3[0];
    }
    __syncthreads();

    // ---------------- coordinates -------------------------------------------
    // Local point p = pp + 32i  ==  dd*8 + c  (dd = d - dbase < 16, c < 8).
    int pp = tid >> 3;                         // 0..31
    int q  = tid & 7;
    int oc    = blockIdx.x >> 4;               // out channel
    int dbase = (blockIdx.x & 15) << 4;        // d-tile base == i-tile base
    float fc = (float)(pp & 7);
    float fo = (float)oc;
    int d0 = dbase + (pp >> 3);                // point i: d = d0 + 4i

    // ---------------- phase 1a: h1[p][4q..4q+3] for 4 points ----------------
    {
        float4 hv[4];
        #pragma unroll
        for (int m = 0; m < 4; m++) {
            int h = (q << 2) + m;
            float zb = fmaf(fc, sW1[h][1], fmaf(fo, sW1[h][2], sb1[h]));
            float w0 = sW1[h][0];
            #pragma unroll
            for (int i = 0; i < 4; i++) {
                float dt = -(float)(d0 + (i << 2)) * (1.0f / 256.0f);
                ((float*)&hv[i])[m] = __sinf(fmaf(dt, w0, zb));  // OMEGA = 1
            }
        }
        #pragma unroll
        for (int i = 0; i < 4; i++)
            *(float4*)&sh1[(pp + (i << 5)) * H1PAD + (q << 2)] = hv[i];
    }
    __syncthreads();

    // ---------------- phase 1b: neurons k=q+8m, 4 points --------------------
    {
        const float* r0 = &sW2[(q     ) * W2PAD];
        const float* r1 = &sW2[(q +  8) * W2PAD];
        const float* r2 = &sW2[(q + 16) * W2PAD];
        const float* r3 = &sW2[(q + 24) * W2PAD];

        float z0[4], z1[4], z2[4], z3[4];
        #pragma unroll
        for (int i = 0; i < 4; i++) {
            z0[i] = sb2[q];
            z1[i] = sb2[q + 8];
            z2[i] = sb2[q + 16];
            z3[i] = sb2[q + 24];
        }

        #pragma unroll
        for (int j = 0; j < 8; j++) {
            float4 h[4];
            #pragma unroll
            for (int i = 0; i < 4; i++)
                h[i] = *(const float4*)&sh1[(pp + (i << 5)) * H1PAD + 4 * j];

            float4 w;
            w = *(const float4*)&r0[4 * j];
            #pragma unroll
            for (int i = 0; i < 4; i++) {
                z0[i] = fmaf(h[i].x, w.x, z0[i]); z0[i] = fmaf(h[i].y, w.y, z0[i]);
                z0[i] = fmaf(h[i].z, w.z, z0[i]); z0[i] = fmaf(h[i].w, w.w, z0[i]);
            }
            w = *(const float4*)&r1[4 * j];
            #pragma unroll
            for (int i = 0; i < 4; i++) {
                z1[i] = fmaf(h[i].x, w.x, z1[i]); z1[i] = fmaf(h[i].y, w.y, z1[i]);
                z1[i] = fmaf(h[i].z, w.z, z1[i]); z1[i] = fmaf(h[i].w, w.w, z1[i]);
            }
            w = *(const float4*)&r2[4 * j];
            #pragma unroll
            for (int i = 0; i < 4; i++) {
                z2[i] = fmaf(h[i].x, w.x, z2[i]); z2[i] = fmaf(h[i].y, w.y, z2[i]);
                z2[i] = fmaf(h[i].z, w.z, z2[i]); z2[i] = fmaf(h[i].w, w.w, z2[i]);
            }
            w = *(const float4*)&r3[4 * j];
            #pragma unroll
            for (int i = 0; i < 4; i++) {
                z3[i] = fmaf(h[i].x, w.x, z3[i]); z3[i] = fmaf(h[i].y, w.y, z3[i]);
                z3[i] = fmaf(h[i].z, w.z, z3[i]); z3[i] = fmaf(h[i].w, w.w, z3[i]);
            }
        }

        float s0 = sw3[q], s1 = sw3[q + 8], s2 = sw3[q + 16], s3 = sw3[q + 24];
        #pragma unroll
        for (int i = 0; i < 4; i++) {
            float acc =        __sinf(z0[i]) * s0;
            acc = fmaf(__sinf(z1[i]), s1, acc);
            acc = fmaf(__sinf(z2[i]), s2, acc);
            acc = fmaf(__sinf(z3[i]), s3, acc);
            acc += __shfl_xor_sync(0xFFFFFFFFu, acc, 1);
            acc += __shfl_xor_sync(0xFFFFFFFFu, acc, 2);
            acc += __shfl_xor_sync(0xFFFFFFFFu, acc, 4);
            if (q == 0)
                sk[pp + (i << 5)] = acc + sb3;    // == sk[dd*8 + c]
        }
    }
    __syncthreads();

    // ---------------- phase 2: conv push (no inter-block sync) --------------
    // Thread j handles output position i = dbase + j; contributions from
    // this block's d-tile: dd in [0,16), valid when dd <= j. x row = j - dd.
    {
        int j = tid;
        int i = dbase + j;
        if (i < LSEQ) {
            const float4* skv = (const float4*)sk;
            float accv = 0.f;
            #pragma unroll
            for (int dd = 0; dd < 16; dd++) {
                float4 k0 = skv[2 * dd];          // broadcast
                float4 k1 = skv[2 * dd + 1];
                int jr = j - dd;
                bool v = jr >= 0;
                int jx = v ? jr : 0;
                float mm = v ? 1.f : 0.f;
                float4 a0 = *(const float4*)&sx[jx * XPAD];
                float4 b0 = *(const float4*)&sx[jx * XPAD + 4];
                float t = k0.x * a0.x;
                t = fmaf(k0.y, a0.y, t);
                t = fmaf(k0.z, a0.z, t);
                t = fmaf(k0.w, a0.w, t);
                t = fmaf(k1.x, b0.x, t);
                t = fmaf(k1.y, b0.y, t);
                t = fmaf(k1.z, b0.z, t);
                t = fmaf(k1.w, b0.w, t);
                accv = fmaf(mm, t, accv);
            }
            atomicAdd(out + i * COUT + oc, accv);  // fire-and-forget REDG
        }
    }
}

// ---------------------------------------------------------------------------
// Launch: async memset node (no SM grid ramp) zeroes out, then push.
// Both graph-capturable. Input order: x, t, v1, g1, b1, v2, g2, b2, w3, b3.
// ---------------------------------------------------------------------------
extern "C" void kernel_launch(void* const* d_in, const int* in_sizes, int n_in,
                              void* d_out, int out_size)
{
    const float* x  = (const float*)d_in[0];
    const float* v1 = (const float*)d_in[2];
    const float* g1 = (const float*)d_in[3];
    const float* b1 = (const float*)d_in[4];
    const float* v2 = (const float*)d_in[5];
    const float* g2 = (const float*)d_in[6];
    const float* b2 = (const float*)d_in[7];
    const float* w3 = (const float*)d_in[8];
    const float* b3 = (const float*)d_in[9];
    float* out = (float*)d_out;

    cudaMemsetAsync(out, 0, (size_t)out_size * sizeof(float), 0);  // memset node
    ckconv_push<<<NBLK, NTHR>>>(x, v1, g1, b1, v2, g2, b2, w3, b3, out);
}